// round 15
// baseline (speedup 1.0000x reference)
#include <cuda_runtime.h>
#include <cstdint>

#define W 8192
#define H 2048
#define NPIX (W * H)
#define THREADS 128
#define PX_PER_BLOCK 1024
#define CHUNKS (PX_PER_BLOCK / THREADS)          // 8
#define NBLOCKS (NPIX / PX_PER_BLOCK)            // 16384
#define IMG_BYTES_PER_BLOCK (PX_PER_BLOCK * 16)  // 16384
#define OUT_BYTES_PER_BLOCK (PX_PER_BLOCK * 12)  // 12288

#define FOV_SPAN     0.5235987755982988f
#define FOV_ABS_DOWN 0.2617993877991494f
#define TWO_PI       6.283185307179586f
#define PI_F         3.141592653589793f

// Rotation by 128 column steps: delta = 128 * 2*pi/8192 = pi/32
#define ROT_C 0.9951847266721969f
#define ROT_S 0.0980171403295606f

__device__ __forceinline__ uint32_t smem_u32(const void* p) {
    uint32_t a;
    asm("{ .reg .u64 t; cvta.to.shared.u64 t, %1; cvt.u32.u64 %0, t; }"
        : "=r"(a) : "l"(p));
    return a;
}

// R13 config with 128-thread blocks: same 16KB tiles and burst sizes
// (geometry is a solved variable), but 13 resident blocks/SM instead of 8
// (smem-capped) -> +62% in-flight TMA load bytes, finer chip-level burst
// interleave — continuing the concurrency direction that won R13.
// Side effect: sincosf count halves (128/block), cutting the 32.3% issue rate.
__global__ void __launch_bounds__(THREADS)
proj_to_pointcloud_kernel(const float* __restrict__ img, float* __restrict__ out) {
    __shared__ alignas(128) float s_buf[PX_PER_BLOCK * 4];   // 16 KB, dual-use
    __shared__ alignas(8)   uint64_t s_mbar;

    int t = threadIdx.x;
    long blockBase = (long)blockIdx.x * PX_PER_BLOCK;        // 1024 | 8192: one row
    int row = (int)(blockBase >> 13);
    int j0  = (int)(blockBase & (W - 1));
    uint32_t mb = smem_u32(&s_mbar);

    if (t == 0) {
        asm volatile("mbarrier.init.shared.b64 [%0], %1;" :: "r"(mb), "r"(1));
    }
    __syncthreads();

    if (t == 0) {
        asm volatile("mbarrier.arrive.expect_tx.shared.b64 _, [%0], %1;"
                     :: "r"(mb), "r"(IMG_BYTES_PER_BLOCK) : "memory");
        asm volatile(
            "cp.async.bulk.shared::cta.global.mbarrier::complete_tx::bytes "
            "[%0], [%1], %2, [%3];"
            :: "r"(smem_u32(s_buf)), "l"(img + (blockBase << 2)),
               "n"(IMG_BYTES_PER_BLOCK), "r"(mb) : "memory");
    }

    // ---- trig, overlapped with the TMA load ----
    float yaw = (float)(j0 + t) * (TWO_PI / (float)W) - PI_F;
    float s, c;
    sincosf(yaw, &s, &c);
    float pitch = (1.0f - (float)row / (float)H) * FOV_SPAN - FOV_ABS_DOWN;
    float sp = sinf(pitch);

    // ---- wait for image tile ----
    asm volatile(
        "{\n\t"
        ".reg .pred P;\n\t"
        "WAIT_%=:\n\t"
        "mbarrier.try_wait.parity.acquire.cta.shared::cta.b64 P, [%0], %1, 0x989680;\n\t"
        "@P bra DONE_%=;\n\t"
        "bra WAIT_%=;\n\t"
        "DONE_%=:\n\t"
        "}" :: "r"(mb), "r"(0) : "memory");

    // ---- extract depths to registers (buffer gets overwritten next) ----
    float d[CHUNKS];
    #pragma unroll
    for (int i = 0; i < CHUNKS; i++) {
        d[i] = s_buf[4 * (i * THREADS + t) + 3];
    }
    __syncthreads();   // all reads done before any xyz overwrite

    #pragma unroll
    for (int i = 0; i < CHUNKS; i++) {
        int p = i * THREADS + t;
        s_buf[3 * p + 0] =  d[i] * c;        // stride-3 scalar STS: conflict-free
        s_buf[3 * p + 1] = -d[i] * s;
        s_buf[3 * p + 2] =  d[i] * sp;
        // advance yaw by 128 columns (pi/32)
        float cn = fmaf(c, ROT_C, -s * ROT_S);
        float sn = fmaf(s, ROT_C,  c * ROT_S);
        c = cn; s = sn;
    }

    __syncthreads();

    if (t == 0) {
        asm volatile("fence.proxy.async.shared::cta;" ::: "memory");
        asm volatile(
            "cp.async.bulk.global.shared::cta.bulk_group [%0], [%1], %2;"
            :: "l"(out + blockBase * 3), "r"(smem_u32(s_buf)),
               "n"(OUT_BYTES_PER_BLOCK) : "memory");
        asm volatile("cp.async.bulk.commit_group;" ::: "memory");
        // keep smem alive until the TMA has read it
        asm volatile("cp.async.bulk.wait_group.read 0;" ::: "memory");
    }
}

extern "C" void kernel_launch(void* const* d_in, const int* in_sizes, int n_in,
                              void* d_out, int out_size) {
    const float* img = (const float*)d_in[0];
    float* out = (float*)d_out;
    proj_to_pointcloud_kernel<<<NBLOCKS, THREADS>>>(img, out);
}